// round 1
// baseline (speedup 1.0000x reference)
#include <cuda_runtime.h>
#include <math.h>

#define Dc 512
#define Ec 256
#define Hc 8
#define Sc 20
#define Bc 8192
#define HDc 64

// ---------------- scratch (device globals; no allocation allowed) ----------
__device__ float g_qh[(size_t)Bc * Dc];          // query @ Wq^T + bq           [B,512]
__device__ float g_qt[(size_t)Bc * Hc * Dc];     // per-head Wk_h^T qh          [B,8,512]
__device__ float g_kbar[(size_t)Bc * Hc * Dc];   // attn-weighted key means     [B,8,512]
__device__ float g_ctx[(size_t)Bc * Dc];         // Wv kbar + bv                [B,512]
__device__ float g_Wc[Ec * Dc];                  // lin_w @ out_proj_w          [256,512]
__device__ float g_bc[Ec];                       // lin_w @ b_o + lin_b

// ---------------- generic fp32 tiled GEMM ---------------------------------
// C[m][n] = sum_k A[m][k] * (TRANS_B ? B[n][k] : B[k][n]) (+bias[n]) (+leaky)
// blockIdx.z applies per-head element offsets aZ/bZ/cZ/biasZ.
// Tiles: BM=128, BN=64, BK=16; 256 threads; each thread 8x4 outputs.
template <bool TRANS_B, bool HAS_BIAS, bool LEAKY>
__global__ __launch_bounds__(256) void gemm_k(
    const float* __restrict__ A, int lda, long aZ,
    const float* __restrict__ Bm, int ldb, long bZ,
    const float* __restrict__ bias, int biasZ,
    float* __restrict__ C, int ldc, long cZ,
    int K)
{
    __shared__ float As[16][132];   // [kk][m], padded (132*4 % 16 == 0)
    __shared__ float Bs[16][64];    // [kk][n]

    const int z  = blockIdx.z;
    A  += (long)z * aZ;
    Bm += (long)z * bZ;
    C  += (long)z * cZ;
    const float* bp = HAS_BIAS ? (bias + (long)z * biasZ) : nullptr;

    const int m0 = blockIdx.y * 128;
    const int n0 = blockIdx.x * 64;
    const int tid = threadIdx.x;
    const int ty = tid >> 4;        // 0..15 -> rows ty*8..ty*8+7
    const int tx = tid & 15;        // 0..15 -> cols tx*4..tx*4+3

    float acc[8][4];
#pragma unroll
    for (int i = 0; i < 8; i++)
#pragma unroll
        for (int j = 0; j < 4; j++) acc[i][j] = 0.0f;

    for (int k0 = 0; k0 < K; k0 += 16) {
        // ---- stage A tile (128 x 16), transposed into As
        {
            const int r = tid >> 2;
            const int c = (tid & 3) * 4;
#pragma unroll
            for (int it = 0; it < 2; it++) {
                const int m = r + it * 64;
                float4 v = *(const float4*)(A + (long)(m0 + m) * lda + k0 + c);
                As[c + 0][m] = v.x; As[c + 1][m] = v.y;
                As[c + 2][m] = v.z; As[c + 3][m] = v.w;
            }
        }
        // ---- stage B tile (16 x 64)
        if (TRANS_B) {
            const int n = tid >> 2;
            const int c = (tid & 3) * 4;
            float4 v = *(const float4*)(Bm + (long)(n0 + n) * ldb + k0 + c);
            Bs[c + 0][n] = v.x; Bs[c + 1][n] = v.y;
            Bs[c + 2][n] = v.z; Bs[c + 3][n] = v.w;
        } else {
            const int kk = tid >> 4;
            const int c  = (tid & 15) * 4;
            *(float4*)&Bs[kk][c] = *(const float4*)(Bm + (long)(k0 + kk) * ldb + n0 + c);
        }
        __syncthreads();

#pragma unroll
        for (int kk = 0; kk < 16; kk++) {
            float4 a0 = *(const float4*)&As[kk][ty * 8];
            float4 a1 = *(const float4*)&As[kk][ty * 8 + 4];
            float4 b0 = *(const float4*)&Bs[kk][tx * 4];
            float a[8] = {a0.x, a0.y, a0.z, a0.w, a1.x, a1.y, a1.z, a1.w};
            float b[4] = {b0.x, b0.y, b0.z, b0.w};
#pragma unroll
            for (int i = 0; i < 8; i++)
#pragma unroll
                for (int j = 0; j < 4; j++)
                    acc[i][j] = fmaf(a[i], b[j], acc[i][j]);
        }
        __syncthreads();
    }

    // ---- epilogue
    float bv[4] = {0, 0, 0, 0};
    if (HAS_BIAS) {
#pragma unroll
        for (int j = 0; j < 4; j++) bv[j] = bp[n0 + tx * 4 + j];
    }
#pragma unroll
    for (int i = 0; i < 8; i++) {
        const int m = m0 + ty * 8 + i;
        float4 v;
        float vv[4];
#pragma unroll
        for (int j = 0; j < 4; j++) {
            float x = acc[i][j] + bv[j];
            if (LEAKY) x = x > 0.0f ? x : 0.01f * x;
            vv[j] = x;
        }
        v.x = vv[0]; v.y = vv[1]; v.z = vv[2]; v.w = vv[3];
        *(float4*)(C + (long)m * ldc + n0 + tx * 4) = v;
    }
}

// ---------------- fused per-node attention: scores -> softmax -> kbar ------
__global__ __launch_bounds__(256) void attn_kernel(
    const float* __restrict__ keys,   // [S,B,D]
    const float* __restrict__ qt,     // [B,H,D]
    float* __restrict__ kbar)         // [B,H,D]
{
    __shared__ float sk[Sc][Dc];       // 40 KB: all 20 keys of this node
    __shared__ float attn_s[Hc][Sc];

    const int b   = blockIdx.x;
    const int tid = threadIdx.x;

    // load 20 x 512 floats, float4-vectorized, coalesced
    for (int t = tid; t < Sc * (Dc / 4); t += 256) {
        const int s = t >> 7;          // /128
        const int v = t & 127;
        ((float4*)&sk[s][0])[v] =
            ((const float4*)(keys + ((size_t)s * Bc + b) * Dc))[v];
    }
    __syncthreads();

    const int w = tid >> 5;            // warp = head
    const int l = tid & 31;

    // q-tilde for this head, register resident (coalesced loads)
    float q[16];
    const float* qrow = qt + (size_t)b * (Hc * Dc) + w * Dc;
#pragma unroll
    for (int i = 0; i < 16; i++) q[i] = qrow[l + 32 * i];

    // scores (dot over D, warp-reduced) and running max
    float sc[Sc];
    float mx = -1e30f;
#pragma unroll
    for (int s = 0; s < Sc; s++) {
        float p = 0.0f;
#pragma unroll
        for (int i = 0; i < 16; i++) p = fmaf(q[i], sk[s][l + 32 * i], p);
#pragma unroll
        for (int o = 16; o > 0; o >>= 1) p += __shfl_xor_sync(0xffffffffu, p, o);
        sc[s] = p * 0.125f;            // scale = 1/sqrt(64)
        mx = fmaxf(mx, sc[s]);
    }

    // softmax over S=20 (redundant across lanes; lane 0 publishes)
    float es[Sc];
    float sum = 0.0f;
#pragma unroll
    for (int s = 0; s < Sc; s++) { es[s] = expf(sc[s] - mx); sum += es[s]; }
    const float inv = 1.0f / sum;
    if (l == 0) {
#pragma unroll
        for (int s = 0; s < Sc; s++) attn_s[w][s] = es[s] * inv;
    }
    __syncthreads();

    // kbar[h][d] = sum_s attn[h][s] * keys[s][d]
    float* kb = kbar + (size_t)b * (Hc * Dc);
#pragma unroll
    for (int r = 0; r < 16; r++) {
        const int idx = tid + 256 * r;           // 0..4095
        const int h = idx >> 9;
        const int d = idx & 511;
        float a = 0.0f;
#pragma unroll
        for (int s = 0; s < Sc; s++) a = fmaf(attn_s[h][s], sk[s][d], a);
        kb[idx] = a;
    }
}

// ---------------- fused bias: bc = lin_w @ b_o + lin_b ---------------------
__global__ void bc_kernel(const float* __restrict__ lin_w,
                          const float* __restrict__ opb,
                          const float* __restrict__ lin_b,
                          float* __restrict__ bc)
{
    const int e = threadIdx.x;
    if (e < Ec) {
        float a = lin_b[e];
        const float* row = lin_w + (size_t)e * Dc;
        for (int d = 0; d < Dc; d++) a = fmaf(row[d], opb[d], a);
        bc[e] = a;
    }
}

// ---------------- launch ---------------------------------------------------
extern "C" void kernel_launch(void* const* d_in, const int* in_sizes, int n_in,
                              void* d_out, int out_size)
{
    const float* query = (const float*)d_in[0];   // [1,B,D]
    const float* keys  = (const float*)d_in[1];   // [S,B,D]
    const float* ipw   = (const float*)d_in[2];   // [3D,D]
    const float* ipb   = (const float*)d_in[3];   // [3D]
    const float* opw   = (const float*)d_in[4];   // [D,D]
    const float* opb   = (const float*)d_in[5];   // [D]
    const float* lw    = (const float*)d_in[6];   // [E,D]
    const float* lb    = (const float*)d_in[7];   // [E]
    float* out = (float*)d_out;                   // [B,E]

    float *qh, *qt, *kbar, *ctx, *Wc, *bc;
    cudaGetSymbolAddress((void**)&qh,   g_qh);
    cudaGetSymbolAddress((void**)&qt,   g_qt);
    cudaGetSymbolAddress((void**)&kbar, g_kbar);
    cudaGetSymbolAddress((void**)&ctx,  g_ctx);
    cudaGetSymbolAddress((void**)&Wc,   g_Wc);
    cudaGetSymbolAddress((void**)&bc,   g_bc);

    dim3 t(256);

    // K0: Wc[e,d] = sum_m lin_w[e,m]*W_o[m,d]   (NN, M=256,N=512,K=512)
    gemm_k<false, false, false><<<dim3(512 / 64, 256 / 128, 1), t>>>(
        lw, Dc, 0,  opw, Dc, 0,  nullptr, 0,  Wc, Dc, 0,  Dc);

    // K0b: bc = lin_w @ b_o + lin_b
    bc_kernel<<<1, 256>>>(lw, opb, lb, bc);

    // K1: qh = query @ Wq^T + bq               (NT, M=8192,N=512,K=512)
    gemm_k<true, true, false><<<dim3(512 / 64, Bc / 128, 1), t>>>(
        query, Dc, 0,  ipw, Dc, 0,  ipb, 0,  qh, Dc, 0,  Dc);

    // K2: qt[b,h,:] = Wk_h^T qh[b,h-slice]     (NN per head, M=8192,N=512,K=64)
    gemm_k<false, false, false><<<dim3(512 / 64, Bc / 128, Hc), t>>>(
        qh, Dc, HDc,
        ipw + (size_t)Dc * Dc, Dc, (long)HDc * Dc,
        nullptr, 0,
        qt, Hc * Dc, Dc,
        HDc);

    // K3: fused scores/softmax/kbar (1 block per node)
    attn_kernel<<<Bc, 256>>>(keys, qt, kbar);

    // K4: ctx[b, h-slice] = Wv_h kbar[b,h,:] + bv_h  (NT per head, M=8192,N=64,K=512)
    gemm_k<true, true, false><<<dim3(1, Bc / 128, Hc), t>>>(
        kbar, Hc * Dc, Dc,
        ipw + (size_t)2 * Dc * Dc, Dc, (long)HDc * Dc,
        ipb + 2 * Dc, HDc,
        ctx, Dc, HDc,
        Dc);

    // K5: y = LeakyReLU(ctx @ Wc^T + bc)       (NT, M=8192,N=256,K=512)
    gemm_k<true, true, true><<<dim3(256 / 64, Bc / 128, 1), t>>>(
        ctx, Dc, 0,  Wc, Dc, 0,  bc, 0,  out, Ec, 0,  Dc);
}

// round 3
// speedup vs baseline: 1.2334x; 1.2334x over previous
#include <cuda_runtime.h>
#include <math.h>

#define Dc 512
#define Ec 256
#define Hc 8
#define Sc 20
#define Bc 8192
#define HDc 64

// ---------------- scratch (device globals; no allocation allowed) ----------
__device__ float g_qh[(size_t)Bc * Dc];          // query @ Wq^T + bq           [B,512]
__device__ float g_qt[(size_t)Bc * Hc * Dc];     // per-head Wk_h^T qh          [B,8,512]
__device__ float g_kbar[(size_t)Bc * Hc * Dc];   // attn-weighted key means     [B,8,512]
__device__ float g_ctx[(size_t)Bc * Dc];         // Wv kbar + bv                [B,512]
__device__ float g_Wc[Ec * Dc];                  // lin_w @ out_proj_w          [256,512]
__device__ float g_Wcp[4 * Ec * Dc];             // split-K partials for Wc
__device__ float g_bc[Ec];                       // lin_w @ b_o + lin_b

// ---------------- fp32 tiled GEMM v2: 128 x BN, BK=16, double-buffered -----
// C[m][n] = sum_k A[m][k] * (TRANS_B ? B[n][k] : B[k][n]) (+bias[n]) (+leaky)
// blockIdx.z applies element offsets aZ/bZ/cZ/biasZ (per-head / split-K).
template <int BN, bool TRANS_B, bool HAS_BIAS, bool LEAKY>
__global__ __launch_bounds__(256) void gemm2(
    const float* __restrict__ A, int lda, long aZ,
    const float* __restrict__ Bm, int ldb, long bZ,
    const float* __restrict__ bias, int biasZ,
    float* __restrict__ C, int ldc, long cZ,
    int K)
{
    constexpr int TN  = BN / 16;        // 8 or 4 cols per thread
    constexpr int NB  = BN / 64;        // B staging float4s per thread
    constexpr int BNP = BN + 4;         // padded stride (132 or 68; %4==0)

    __shared__ float As[2][16][132];
    __shared__ float Bs[2][16][BNP];

    const int z = blockIdx.z;
    A  += (long)z * aZ;
    Bm += (long)z * bZ;
    C  += (long)z * cZ;
    const float* bp = HAS_BIAS ? (bias + (long)z * biasZ) : nullptr;

    const int m0  = blockIdx.y * 128;
    const int n0  = blockIdx.x * BN;
    const int tid = threadIdx.x;
    const int tx  = tid & 15;           // n group
    const int ty  = tid >> 4;           // m group (rows ty*8..+7)

    // staging thread mapping
    const int ar  = tid >> 2;           // 0..63
    const int ac  = (tid & 3) << 2;     // 0,4,8,12
    const int bk  = tid >> 4;           // 0..15   (!TRANS_B)
    const int bcc = (tid & 15) << 2;    // 0..60   (!TRANS_B)

    float4 aR[2], bR[NB];

    auto ldTile = [&](int k0) {
        aR[0] = *(const float4*)(A + (long)(m0 + ar) * lda + k0 + ac);
        aR[1] = *(const float4*)(A + (long)(m0 + ar + 64) * lda + k0 + ac);
        if (TRANS_B) {
#pragma unroll
            for (int u = 0; u < NB; u++)
                bR[u] = *(const float4*)(Bm + (long)(n0 + ar + 64 * u) * ldb + k0 + ac);
        } else {
#pragma unroll
            for (int u = 0; u < NB; u++)
                bR[u] = *(const float4*)(Bm + (long)(k0 + bk) * ldb + n0 + bcc + 64 * u);
        }
    };
    auto stTile = [&](int buf) {
        As[buf][ac + 0][ar]      = aR[0].x;
        As[buf][ac + 1][ar]      = aR[0].y;
        As[buf][ac + 2][ar]      = aR[0].z;
        As[buf][ac + 3][ar]      = aR[0].w;
        As[buf][ac + 0][ar + 64] = aR[1].x;
        As[buf][ac + 1][ar + 64] = aR[1].y;
        As[buf][ac + 2][ar + 64] = aR[1].z;
        As[buf][ac + 3][ar + 64] = aR[1].w;
        if (TRANS_B) {
#pragma unroll
            for (int u = 0; u < NB; u++) {
                Bs[buf][ac + 0][ar + 64 * u] = bR[u].x;
                Bs[buf][ac + 1][ar + 64 * u] = bR[u].y;
                Bs[buf][ac + 2][ar + 64 * u] = bR[u].z;
                Bs[buf][ac + 3][ar + 64 * u] = bR[u].w;
            }
        } else {
#pragma unroll
            for (int u = 0; u < NB; u++)
                *(float4*)&Bs[buf][bk][bcc + 64 * u] = bR[u];
        }
    };

    float acc[8][TN];
#pragma unroll
    for (int i = 0; i < 8; i++)
#pragma unroll
        for (int j = 0; j < TN; j++) acc[i][j] = 0.0f;

    ldTile(0);
    stTile(0);
    __syncthreads();

    int buf = 0;
    for (int k0 = 16;; k0 += 16) {
        const bool last = (k0 >= K);
        if (!last) ldTile(k0);

#pragma unroll
        for (int kk = 0; kk < 16; kk++) {
            float4 x0 = *(const float4*)&As[buf][kk][ty * 8];
            float4 x1 = *(const float4*)&As[buf][kk][ty * 8 + 4];
            float a[8] = {x0.x, x0.y, x0.z, x0.w, x1.x, x1.y, x1.z, x1.w};
            float b[TN];
#pragma unroll
            for (int u = 0; u < TN / 4; u++) {
                float4 y = *(const float4*)&Bs[buf][kk][tx * TN + 4 * u];
                b[4 * u + 0] = y.x; b[4 * u + 1] = y.y;
                b[4 * u + 2] = y.z; b[4 * u + 3] = y.w;
            }
#pragma unroll
            for (int i = 0; i < 8; i++)
#pragma unroll
                for (int j = 0; j < TN; j++)
                    acc[i][j] = fmaf(a[i], b[j], acc[i][j]);
        }
        if (last) break;
        stTile(buf ^ 1);
        __syncthreads();
        buf ^= 1;
    }

    // ---- epilogue
    float bv[TN];
#pragma unroll
    for (int j = 0; j < TN; j++) bv[j] = HAS_BIAS ? bp[n0 + tx * TN + j] : 0.0f;

#pragma unroll
    for (int i = 0; i < 8; i++) {
        const int m = m0 + ty * 8 + i;
#pragma unroll
        for (int u = 0; u < TN / 4; u++) {
            float4 v;
            float vv[4];
#pragma unroll
            for (int j = 0; j < 4; j++) {
                float x = acc[i][4 * u + j] + bv[4 * u + j];
                if (LEAKY) x = x > 0.0f ? x : 0.01f * x;
                vv[j] = x;
            }
            v.x = vv[0]; v.y = vv[1]; v.z = vv[2]; v.w = vv[3];
            *(float4*)(C + (long)m * ldc + n0 + tx * TN + 4 * u) = v;
        }
    }
}

// ---------------- fused per-node attention: scores -> softmax -> kbar ------
__global__ __launch_bounds__(256) void attn2(
    const float* __restrict__ keys,   // [S,B,D]
    const float* __restrict__ qt,     // [B,H,D]
    float* __restrict__ kbar)         // [B,H,D]
{
    __shared__ __align__(16) float sk[Sc][Dc];     // 40 KB
    __shared__ __align__(16) float attnT[Sc][Hc];  // transposed weights

    const int b   = blockIdx.x;
    const int tid = threadIdx.x;

    // stage keys: 20 x 128 float4, coalesced
#pragma unroll
    for (int i = 0; i < 10; i++) {
        const int idx = tid + 256 * i;          // 0..2559
        const int s = idx >> 7;
        const int v = idx & 127;
        ((float4*)sk)[idx] =
            ((const float4*)(keys + ((size_t)s * Bc + b) * Dc))[v];
    }
    __syncthreads();

    const int w = tid >> 5;            // warp = head
    const int l = tid & 31;

    // q-tilde fragment: d = 128*j + 4*l + c
    const float* qrow = qt + (size_t)b * (Hc * Dc) + w * Dc;
    float4 qf[4];
#pragma unroll
    for (int j = 0; j < 4; j++)
        qf[j] = *(const float4*)(qrow + 128 * j + 4 * l);

    // scores
    float sc[Sc];
    float mx = -1e30f;
#pragma unroll
    for (int s = 0; s < Sc; s++) {
        const float4* kr = (const float4*)&sk[s][0];
        float p = 0.0f;
#pragma unroll
        for (int j = 0; j < 4; j++) {
            float4 kv = kr[32 * j + l];
            p = fmaf(qf[j].x, kv.x, p);
            p = fmaf(qf[j].y, kv.y, p);
            p = fmaf(qf[j].z, kv.z, p);
            p = fmaf(qf[j].w, kv.w, p);
        }
#pragma unroll
        for (int o = 16; o > 0; o >>= 1) p += __shfl_xor_sync(0xffffffffu, p, o);
        sc[s] = p * 0.125f;            // 1/sqrt(64)
        mx = fmaxf(mx, sc[s]);
    }

    // softmax (redundant across lanes; lane 0 publishes)
    float sum = 0.0f;
#pragma unroll
    for (int s = 0; s < Sc; s++) { sc[s] = expf(sc[s] - mx); sum += sc[s]; }
    const float inv = 1.0f / sum;
    if (l == 0) {
#pragma unroll
        for (int s = 0; s < Sc; s++) attnT[s][w] = sc[s] * inv;
    }
    __syncthreads();

    // kbar: thread owns d = 2*tid, 2*tid+1; accumulates all 8 heads
    float2 acc[Hc];
#pragma unroll
    for (int h = 0; h < Hc; h++) { acc[h].x = 0.0f; acc[h].y = 0.0f; }

    const float2* sk2 = (const float2*)sk;
#pragma unroll
    for (int s = 0; s < Sc; s++) {
        const float2 kv = sk2[s * (Dc / 2) + tid];
        const float4 a0 = *(const float4*)&attnT[s][0];
        const float4 a1 = *(const float4*)&attnT[s][4];
        acc[0].x = fmaf(a0.x, kv.x, acc[0].x); acc[0].y = fmaf(a0.x, kv.y, acc[0].y);
        acc[1].x = fmaf(a0.y, kv.x, acc[1].x); acc[1].y = fmaf(a0.y, kv.y, acc[1].y);
        acc[2].x = fmaf(a0.z, kv.x, acc[2].x); acc[2].y = fmaf(a0.z, kv.y, acc[2].y);
        acc[3].x = fmaf(a0.w, kv.x, acc[3].x); acc[3].y = fmaf(a0.w, kv.y, acc[3].y);
        acc[4].x = fmaf(a1.x, kv.x, acc[4].x); acc[4].y = fmaf(a1.x, kv.y, acc[4].y);
        acc[5].x = fmaf(a1.y, kv.x, acc[5].x); acc[5].y = fmaf(a1.y, kv.y, acc[5].y);
        acc[6].x = fmaf(a1.z, kv.x, acc[6].x); acc[6].y = fmaf(a1.z, kv.y, acc[6].y);
        acc[7].x = fmaf(a1.w, kv.x, acc[7].x); acc[7].y = fmaf(a1.w, kv.y, acc[7].y);
    }

    float* kb = kbar + (size_t)b * (Hc * Dc);
#pragma unroll
    for (int h = 0; h < Hc; h++)
        *(float2*)(kb + h * Dc + 2 * tid) = acc[h];
}

// ---------------- Wc split-K reduction -------------------------------------
__global__ void wc_reduce(const float4* __restrict__ p, float4* __restrict__ o)
{
    const int i = blockIdx.x * 256 + threadIdx.x;      // 0..32767
    float4 a = p[i], b = p[i + 32768], c = p[i + 65536], d = p[i + 98304];
    float4 r;
    r.x = a.x + b.x + c.x + d.x;
    r.y = a.y + b.y + c.y + d.y;
    r.z = a.z + b.z + c.z + d.z;
    r.w = a.w + b.w + c.w + d.w;
    o[i] = r;
}

// ---------------- fused bias: bc = lin_w @ b_o + lin_b ---------------------
__global__ void bc_kernel(const float* __restrict__ lin_w,
                          const float* __restrict__ opb,
                          const float* __restrict__ lin_b,
                          float* __restrict__ bc)
{
    const int e = threadIdx.x;
    if (e < Ec) {
        float a = lin_b[e];
        const float4* row = (const float4*)(lin_w + (size_t)e * Dc);
        const float4* ob  = (const float4*)opb;
        for (int d = 0; d < Dc / 4; d++) {
            float4 r = row[d], v = ob[d];
            a = fmaf(r.x, v.x, a); a = fmaf(r.y, v.y, a);
            a = fmaf(r.z, v.z, a); a = fmaf(r.w, v.w, a);
        }
        bc[e] = a;
    }
}

// ---------------- launch ---------------------------------------------------
extern "C" void kernel_launch(void* const* d_in, const int* in_sizes, int n_in,
                              void* d_out, int out_size)
{
    const float* query = (const float*)d_in[0];   // [1,B,D]
    const float* keys  = (const float*)d_in[1];   // [S,B,D]
    const float* ipw   = (const float*)d_in[2];   // [3D,D]
    const float* ipb   = (const float*)d_in[3];   // [3D]
    const float* opw   = (const float*)d_in[4];   // [D,D]
    const float* opb   = (const float*)d_in[5];   // [D]
    const float* lw    = (const float*)d_in[6];   // [E,D]
    const float* lb    = (const float*)d_in[7];   // [E]
    float* out = (float*)d_out;                   // [B,E]

    float *qh, *qt, *kbar, *ctx, *Wc, *Wcp, *bc;
    cudaGetSymbolAddress((void**)&qh,   g_qh);
    cudaGetSymbolAddress((void**)&qt,   g_qt);
    cudaGetSymbolAddress((void**)&kbar, g_kbar);
    cudaGetSymbolAddress((void**)&ctx,  g_ctx);
    cudaGetSymbolAddress((void**)&Wc,   g_Wc);
    cudaGetSymbolAddress((void**)&Wcp,  g_Wcp);
    cudaGetSymbolAddress((void**)&bc,   g_bc);

    dim3 t(256);

    // K0: Wc = lin_w @ W_o, split-K z=4 (NN, M=256, N=512, K=128/part)
    gemm2<128, false, false, false><<<dim3(4, 2, 4), t>>>(
        lw, Dc, 128,
        opw, Dc, (long)128 * Dc,
        nullptr, 0,
        Wcp, Dc, (long)Ec * Dc,
        128);
    wc_reduce<<<128, 256>>>((const float4*)Wcp, (float4*)Wc);
    bc_kernel<<<1, 256>>>(lw, opb, lb, bc);

    // K1: qh = query @ Wq^T + bq               (NT, M=8192, N=512, K=512)
    gemm2<128, true, true, false><<<dim3(4, Bc / 128, 1), t>>>(
        query, Dc, 0,  ipw, Dc, 0,  ipb, 0,  qh, Dc, 0,  Dc);

    // K2: qt[b,h,:] = Wk_h^T qh_h              (NN per head, M=8192, N=512, K=64)
    gemm2<128, false, false, false><<<dim3(4, Bc / 128, Hc), t>>>(
        qh, Dc, HDc,
        ipw + (size_t)Dc * Dc, Dc, (long)HDc * Dc,
        nullptr, 0,
        qt, Hc * Dc, Dc,
        HDc);

    // K3: fused scores/softmax/kbar (1 block per node)
    attn2<<<Bc, 256>>>(keys, qt, kbar);

    // K4: ctx[b,h-slice] = Wv_h kbar_h + bv    (NT per head, M=8192, N=64, K=512)
    gemm2<64, true, true, false><<<dim3(1, Bc / 128, Hc), t>>>(
        kbar, Hc * Dc, Dc,
        ipw + (size_t)2 * Dc * Dc, Dc, (long)HDc * Dc,
        ipb + 2 * Dc, HDc,
        ctx, Dc, HDc,
        Dc);

    // K5: y = LeakyReLU(ctx @ Wc^T + bc)       (NT, M=8192, N=256, K=512)
    gemm2<64, true, true, true><<<dim3(4, Bc / 128, 1), t>>>(
        ctx, Dc, 0,  Wc, Dc, 0,  bc, 0,  out, Ec, 0,  Dc);
}

// round 6
// speedup vs baseline: 1.6660x; 1.3507x over previous
#include <cuda_runtime.h>
#include <cuda_bf16.h>
#include <cstdint>
#include <math.h>

#define Dc 512
#define Ec 256
#define Hc 8
#define Sc 20
#define Bc 8192
#define HDc 64

// ---------------- scratch (device globals; no allocation allowed) ----------
__device__ float g_qh[(size_t)Bc * Dc];            // query @ Wq^T + bq        [B,512]
__device__ float g_qt[(size_t)Bc * Hc * Dc];       // per-head Wk_h^T qh       [B,8,512]
__device__ float g_kbar[(size_t)Bc * Hc * Dc];     // attn-weighted key means  [B,8,512]
__device__ float g_ctx[(size_t)Bc * Dc];           // Wv kbar + bv             [B,512]
__device__ float g_Wc[Ec * Dc];                    // lin_w @ out_proj_w       [256,512]
__device__ float g_bc[Ec];                         // lin_w @ b_o + lin_b
__device__ float g_WkT[Dc * Dc];                   // Wk^T  (n-major, k contig)
__device__ float g_opwT[Dc * Dc];                  // out_proj_w^T

// ---------------- bf16 mma.sync helper (sm_80+, works on compute_100) ------
__device__ __forceinline__ void mma16816(float* c,
                                         const uint32_t* a, const uint32_t* b) {
    asm volatile(
        "mma.sync.aligned.m16n8k16.row.col.f32.bf16.bf16.f32 "
        "{%0,%1,%2,%3}, {%4,%5,%6,%7}, {%8,%9}, {%0,%1,%2,%3};"
        : "+f"(c[0]), "+f"(c[1]), "+f"(c[2]), "+f"(c[3])
        : "r"(a[0]), "r"(a[1]), "r"(a[2]), "r"(a[3]), "r"(b[0]), "r"(b[1]));
}

// hi/lo bf16 split of a float4 -> two packed uint2 (4 bf16 each)
__device__ __forceinline__ void cvt_split(float4 v, uint2& hi, uint2& lo) {
    __nv_bfloat16 hx = __float2bfloat16(v.x), hy = __float2bfloat16(v.y);
    __nv_bfloat16 hz = __float2bfloat16(v.z), hw = __float2bfloat16(v.w);
    __nv_bfloat16 lx = __float2bfloat16(v.x - __bfloat162float(hx));
    __nv_bfloat16 ly = __float2bfloat16(v.y - __bfloat162float(hy));
    __nv_bfloat16 lz = __float2bfloat16(v.z - __bfloat162float(hz));
    __nv_bfloat16 lw = __float2bfloat16(v.w - __bfloat162float(hw));
    __nv_bfloat162 h0 = __halves2bfloat162(hx, hy), h1 = __halves2bfloat162(hz, hw);
    __nv_bfloat162 l0 = __halves2bfloat162(lx, ly), l1 = __halves2bfloat162(lz, lw);
    hi.x = *(uint32_t*)&h0; hi.y = *(uint32_t*)&h1;
    lo.x = *(uint32_t*)&l0; lo.y = *(uint32_t*)&l1;
}

// ---------------- bf16 hi/lo NT GEMM on mma.sync ---------------------------
// C[m][n] = sum_k A[m][k]*B[n][k] (both K-contiguous), + bias, + leaky.
// Block 128 x BN, BK=32. 8 warps: 2(m) x 4(n); warp tile 64 x (BN/4).
// hi*hi + hi*lo + lo*hi accumulation in fp32.
template <int BN, bool HAS_BIAS, bool LEAKY>
__global__ __launch_bounds__(256) void mgemm(
    const float* __restrict__ A, int lda, long aZ,
    const float* __restrict__ Bm, int ldb, long bZ,
    const float* __restrict__ bias, int biasZ,
    float* __restrict__ C, int ldc, long cZ,
    int K)
{
    constexpr int P  = 40;              // smem pitch in bf16 (32 + 8 pad)
    constexpr int NF = BN / 32;         // n8-frags per warp (warp n-tile = BN/4)

    __shared__ __align__(16) uint16_t sAhi[128 * P];
    __shared__ __align__(16) uint16_t sAlo[128 * P];
    __shared__ __align__(16) uint16_t sBhi[BN * P];
    __shared__ __align__(16) uint16_t sBlo[BN * P];

    const int tid  = threadIdx.x;
    const int wid  = tid >> 5;
    const int lane = tid & 31;
    const int g    = lane >> 2;         // 0..7
    const int tig  = lane & 3;          // 0..3
    const int wm   = wid & 1;           // m-warp (0..1)
    const int wn   = wid >> 1;          // n-warp (0..3)

    const int z = blockIdx.z;
    A  += (long)z * aZ;
    Bm += (long)z * bZ;
    C  += (long)z * cZ;
    const float* bp = HAS_BIAS ? (bias + (long)z * biasZ) : nullptr;
    const int m0 = blockIdx.y * 128;
    const int n0 = blockIdx.x * BN;

    float acc[4][NF][4];
#pragma unroll
    for (int mf = 0; mf < 4; mf++)
#pragma unroll
        for (int nf = 0; nf < NF; nf++)
#pragma unroll
            for (int j = 0; j < 4; j++) acc[mf][nf][j] = 0.0f;

    const int nchunk = K >> 5;          // BK = 32
    for (int c = 0; c < nchunk; c++) {
        const int k0 = c << 5;
        __syncthreads();                // smem reuse guard

        // ---- stage A: 128 rows x 32 cols (1024 float4, 4 per thread)
#pragma unroll
        for (int i = 0; i < 4; i++) {
            const int idx = tid + 256 * i;
            const int row = idx >> 3;
            const int c4  = (idx & 7) << 2;
            float4 v = *(const float4*)(A + (long)(m0 + row) * lda + k0 + c4);
            uint2 hi, lo;
            cvt_split(v, hi, lo);
            *(uint2*)(sAhi + row * P + c4) = hi;
            *(uint2*)(sAlo + row * P + c4) = lo;
        }
        // ---- stage B: BN rows x 32 cols
#pragma unroll
        for (int i = 0; i < BN / 32; i++) {
            const int idx = tid + 256 * i;
            const int row = idx >> 3;
            const int c4  = (idx & 7) << 2;
            float4 v = *(const float4*)(Bm + (long)(n0 + row) * ldb + k0 + c4);
            uint2 hi, lo;
            cvt_split(v, hi, lo);
            *(uint2*)(sBhi + row * P + c4) = hi;
            *(uint2*)(sBlo + row * P + c4) = lo;
        }
        __syncthreads();

        // ---- compute: two k16 steps
#pragma unroll
        for (int kk = 0; kk < 32; kk += 16) {
            const int co = kk + 2 * tig;
            uint32_t ah[4][4], al[4][4];
#pragma unroll
            for (int mf = 0; mf < 4; mf++) {
                const int r = wm * 64 + mf * 16 + g;
                ah[mf][0] = *(const uint32_t*)(sAhi + r * P + co);
                ah[mf][1] = *(const uint32_t*)(sAhi + (r + 8) * P + co);
                ah[mf][2] = *(const uint32_t*)(sAhi + r * P + co + 8);
                ah[mf][3] = *(const uint32_t*)(sAhi + (r + 8) * P + co + 8);
                al[mf][0] = *(const uint32_t*)(sAlo + r * P + co);
                al[mf][1] = *(const uint32_t*)(sAlo + (r + 8) * P + co);
                al[mf][2] = *(const uint32_t*)(sAlo + r * P + co + 8);
                al[mf][3] = *(const uint32_t*)(sAlo + (r + 8) * P + co + 8);
            }
            uint32_t bh[NF][2], bl[NF][2];
#pragma unroll
            for (int nf = 0; nf < NF; nf++) {
                const int n = wn * (BN / 4) + nf * 8 + g;
                bh[nf][0] = *(const uint32_t*)(sBhi + n * P + co);
                bh[nf][1] = *(const uint32_t*)(sBhi + n * P + co + 8);
                bl[nf][0] = *(const uint32_t*)(sBlo + n * P + co);
                bl[nf][1] = *(const uint32_t*)(sBlo + n * P + co + 8);
            }
#pragma unroll
            for (int mf = 0; mf < 4; mf++)
#pragma unroll
                for (int nf = 0; nf < NF; nf++) {
                    mma16816(acc[mf][nf], ah[mf], bh[nf]);
                    mma16816(acc[mf][nf], ah[mf], bl[nf]);
                    mma16816(acc[mf][nf], al[mf], bh[nf]);
                }
        }
    }

    // ---- epilogue
#pragma unroll
    for (int mf = 0; mf < 4; mf++) {
        const int row = m0 + wm * 64 + mf * 16 + g;
#pragma unroll
        for (int nf = 0; nf < NF; nf++) {
            const int col = n0 + wn * (BN / 4) + nf * 8 + 2 * tig;
            float b0 = 0.0f, b1 = 0.0f;
            if (HAS_BIAS) { b0 = bp[col]; b1 = bp[col + 1]; }
            float x0 = acc[mf][nf][0] + b0, x1 = acc[mf][nf][1] + b1;
            float x2 = acc[mf][nf][2] + b0, x3 = acc[mf][nf][3] + b1;
            if (LEAKY) {
                x0 = x0 > 0.0f ? x0 : 0.01f * x0;
                x1 = x1 > 0.0f ? x1 : 0.01f * x1;
                x2 = x2 > 0.0f ? x2 : 0.01f * x2;
                x3 = x3 > 0.0f ? x3 : 0.01f * x3;
            }
            float2 v0; v0.x = x0; v0.y = x1;
            float2 v1; v1.x = x2; v1.y = x3;
            *(float2*)(C + (long)row * ldc + col)       = v0;
            *(float2*)(C + (long)(row + 8) * ldc + col) = v1;
        }
    }
}

// ---------------- 512x512 transpose ----------------------------------------
__global__ void transp512(const float* __restrict__ in, float* __restrict__ out)
{
    __shared__ float t[32][33];
    const int x = blockIdx.x * 32 + threadIdx.x;
    const int y0 = blockIdx.y * 32;
#pragma unroll
    for (int r = threadIdx.y; r < 32; r += 8)
        t[r][threadIdx.x] = in[(y0 + r) * 512 + x];
    __syncthreads();
    const int xo = blockIdx.y * 32 + threadIdx.x;
#pragma unroll
    for (int r = threadIdx.y; r < 32; r += 8)
        out[(blockIdx.x * 32 + r) * 512 + xo] = t[threadIdx.x][r];
}

// ---------------- fused per-node attention: scores -> softmax -> kbar ------
__global__ __launch_bounds__(256) void attn2(
    const float* __restrict__ keys,   // [S,B,D]
    const float* __restrict__ qt,     // [B,H,D]
    float* __restrict__ kbar)         // [B,H,D]
{
    __shared__ __align__(16) float sk[Sc][Dc];     // 40 KB
    __shared__ __align__(16) float attnT[Sc][Hc];  // transposed weights

    const int b   = blockIdx.x;
    const int tid = threadIdx.x;

#pragma unroll
    for (int i = 0; i < 10; i++) {
        const int idx = tid + 256 * i;
        const int s = idx >> 7;
        const int v = idx & 127;
        ((float4*)sk)[idx] = ((const float4*)(keys + ((size_t)s * Bc + b) * Dc))[v];
    }
    __syncthreads();

    const int w = tid >> 5;
    const int l = tid & 31;

    const float* qrow = qt + (size_t)b * (Hc * Dc) + w * Dc;
    float4 qf[4];
#pragma unroll
    for (int j = 0; j < 4; j++)
        qf[j] = *(const float4*)(qrow + 128 * j + 4 * l);

    float sc[Sc];
    float mx = -1e30f;
#pragma unroll
    for (int s = 0; s < Sc; s++) {
        const float4* kr = (const float4*)&sk[s][0];
        float p = 0.0f;
#pragma unroll
        for (int j = 0; j < 4; j++) {
            float4 kv = kr[32 * j + l];
            p = fmaf(qf[j].x, kv.x, p);
            p = fmaf(qf[j].y, kv.y, p);
            p = fmaf(qf[j].z, kv.z, p);
            p = fmaf(qf[j].w, kv.w, p);
        }
#pragma unroll
        for (int o = 16; o > 0; o >>= 1) p += __shfl_xor_sync(0xffffffffu, p, o);
        sc[s] = p * 0.125f;
        mx = fmaxf(mx, sc[s]);
    }

    float sum = 0.0f;
#pragma unroll
    for (int s = 0; s < Sc; s++) { sc[s] = expf(sc[s] - mx); sum += sc[s]; }
    const float inv = 1.0f / sum;
    if (l == 0) {
#pragma unroll
        for (int s = 0; s < Sc; s++) attnT[s][w] = sc[s] * inv;
    }
    __syncthreads();

    float2 acc[Hc];
#pragma unroll
    for (int h = 0; h < Hc; h++) { acc[h].x = 0.0f; acc[h].y = 0.0f; }

    const float2* sk2 = (const float2*)sk;
#pragma unroll
    for (int s = 0; s < Sc; s++) {
        const float2 kv = sk2[s * (Dc / 2) + tid];
        const float4 a0 = *(const float4*)&attnT[s][0];
        const float4 a1 = *(const float4*)&attnT[s][4];
        acc[0].x = fmaf(a0.x, kv.x, acc[0].x); acc[0].y = fmaf(a0.x, kv.y, acc[0].y);
        acc[1].x = fmaf(a0.y, kv.x, acc[1].x); acc[1].y = fmaf(a0.y, kv.y, acc[1].y);
        acc[2].x = fmaf(a0.z, kv.x, acc[2].x); acc[2].y = fmaf(a0.z, kv.y, acc[2].y);
        acc[3].x = fmaf(a0.w, kv.x, acc[3].x); acc[3].y = fmaf(a0.w, kv.y, acc[3].y);
        acc[4].x = fmaf(a1.x, kv.x, acc[4].x); acc[4].y = fmaf(a1.x, kv.y, acc[4].y);
        acc[5].x = fmaf(a1.y, kv.x, acc[5].x); acc[5].y = fmaf(a1.y, kv.y, acc[5].y);
        acc[6].x = fmaf(a1.z, kv.x, acc[6].x); acc[6].y = fmaf(a1.z, kv.y, acc[6].y);
        acc[7].x = fmaf(a1.w, kv.x, acc[7].x); acc[7].y = fmaf(a1.w, kv.y, acc[7].y);
    }

    float* kb = kbar + (size_t)b * (Hc * Dc);
#pragma unroll
    for (int h = 0; h < Hc; h++)
        *(float2*)(kb + h * Dc + 2 * tid) = acc[h];
}

// ---------------- fused bias: bc = lin_w @ b_o + lin_b ---------------------
__global__ void bc_kernel(const float* __restrict__ lin_w,
                          const float* __restrict__ opb,
                          const float* __restrict__ lin_b,
                          float* __restrict__ bc)
{
    const int e = threadIdx.x;
    if (e < Ec) {
        float a = lin_b[e];
        const float4* row = (const float4*)(lin_w + (size_t)e * Dc);
        const float4* ob  = (const float4*)opb;
        for (int d = 0; d < Dc / 4; d++) {
            float4 r = row[d], v = ob[d];
            a = fmaf(r.x, v.x, a); a = fmaf(r.y, v.y, a);
            a = fmaf(r.z, v.z, a); a = fmaf(r.w, v.w, a);
        }
        bc[e] = a;
    }
}

// ---------------- launch ---------------------------------------------------
extern "C" void kernel_launch(void* const* d_in, const int* in_sizes, int n_in,
                              void* d_out, int out_size)
{
    const float* query = (const float*)d_in[0];   // [1,B,D]
    const float* keys  = (const float*)d_in[1];   // [S,B,D]
    const float* ipw   = (const float*)d_in[2];   // [3D,D]
    const float* ipb   = (const float*)d_in[3];   // [3D]
    const float* opw   = (const float*)d_in[4];   // [D,D]
    const float* opb   = (const float*)d_in[5];   // [D]
    const float* lw    = (const float*)d_in[6];   // [E,D]
    const float* lb    = (const float*)d_in[7];   // [E]
    float* out = (float*)d_out;                   // [B,E]

    float *qh, *qt, *kbar, *ctx, *Wc, *bc, *WkT, *opwT;
    cudaGetSymbolAddress((void**)&qh,   g_qh);
    cudaGetSymbolAddress((void**)&qt,   g_qt);
    cudaGetSymbolAddress((void**)&kbar, g_kbar);
    cudaGetSymbolAddress((void**)&ctx,  g_ctx);
    cudaGetSymbolAddress((void**)&Wc,   g_Wc);
    cudaGetSymbolAddress((void**)&bc,   g_bc);
    cudaGetSymbolAddress((void**)&WkT,  g_WkT);
    cudaGetSymbolAddress((void**)&opwT, g_opwT);

    dim3 t(256);

    // T: transposes (WkT = Wk^T, opwT = out_proj_w^T) + fused bias
    transp512<<<dim3(16, 16), dim3(32, 8)>>>(ipw + (size_t)Dc * Dc, WkT);
    transp512<<<dim3(16, 16), dim3(32, 8)>>>(opw, opwT);
    bc_kernel<<<1, 256>>>(lw, opb, lb, bc);

    // K0: Wc = lin_w @ opwT^T   (NT, M=256, N=512, K=512)
    mgemm<128, false, false><<<dim3(4, 2, 1), t>>>(
        lw, Dc, 0,  opwT, Dc, 0,  nullptr, 0,  Wc, Dc, 0,  Dc);

    // K1: qh = query @ Wq^T + bq   (NT, M=8192, N=512, K=512)
    mgemm<128, true, false><<<dim3(4, Bc / 128, 1), t>>>(
        query, Dc, 0,  ipw, Dc, 0,  ipb, 0,  qh, Dc, 0,  Dc);

    // K2: qt[b,h,:] = Wk_h^T qh_h  (NT per head, M=8192, N=512, K=64)
    mgemm<128, false, false><<<dim3(4, Bc / 128, Hc), t>>>(
        qh, Dc, HDc,
        WkT, Dc, HDc,
        nullptr, 0,
        qt, Hc * Dc, Dc,
        HDc);

    // K3: fused scores/softmax/kbar
    attn2<<<Bc, 256>>>(keys, qt, kbar);

    // K4: ctx[b,h-slice] = Wv_h kbar_h + bv (NT per head, M=8192, N=64, K=512)
    mgemm<64, true, false><<<dim3(1, Bc / 128, Hc), t>>>(
        kbar, Hc * Dc, Dc,
        ipw + (size_t)2 * Dc * Dc, Dc, (long)HDc * Dc,
        ipb + 2 * Dc, HDc,
        ctx, Dc, HDc,
        Dc);

    // K5: y = LeakyReLU(ctx @ Wc^T + bc)  (NT, M=8192, N=256, K=512)
    mgemm<128, true, true><<<dim3(2, Bc / 128, 1), t>>>(
        ctx, Dc, 0,  Wc, Dc, 0,  bc, 0,  out, Ec, 0,  Dc);
}

// round 7
// speedup vs baseline: 1.7575x; 1.0549x over previous
#include <cuda_runtime.h>
#include <cuda_bf16.h>
#include <cstdint>
#include <math.h>

#define Dc 512
#define Ec 256
#define Hc 8
#define Sc 20
#define Bc 8192
#define HDc 64

// ---------------- scratch (device globals; no allocation allowed) ----------
__device__ float g_qh[(size_t)Bc * Dc];            // query @ Wq^T + bq        [B,512]
__device__ float g_qt[(size_t)Bc * Hc * Dc];       // per-head Wk_h^T qh       [B,8,512]
__device__ float g_kbar[(size_t)Bc * Hc * Dc];     // attn-weighted key means  [B,8,512]
__device__ float g_ctx[(size_t)Bc * Dc];           // Wv kbar + bv             [B,512]
__device__ float g_Wc[Ec * Dc];                    // lin_w @ out_proj_w       [256,512]
__device__ float g_Wcp[4 * Ec * Dc];               // split-K partials for Wc
__device__ float g_bc[Ec];                         // lin_w @ b_o + lin_b
__device__ float g_WkT[Dc * Dc];                   // Wk^T  (n-major, k contig)
__device__ float g_opwT[Dc * Dc];                  // out_proj_w^T

// ---------------- bf16 mma.sync helper (sm_80+, works on compute_100) ------
__device__ __forceinline__ void mma16816(float* c,
                                         const uint32_t* a, const uint32_t* b) {
    asm volatile(
        "mma.sync.aligned.m16n8k16.row.col.f32.bf16.bf16.f32 "
        "{%0,%1,%2,%3}, {%4,%5,%6,%7}, {%8,%9}, {%0,%1,%2,%3};"
        : "+f"(c[0]), "+f"(c[1]), "+f"(c[2]), "+f"(c[3])
        : "r"(a[0]), "r"(a[1]), "r"(a[2]), "r"(a[3]), "r"(b[0]), "r"(b[1]));
}

// hi/lo bf16 split of a float4 -> two packed uint2 (4 bf16 each)
__device__ __forceinline__ void cvt_split(float4 v, uint2& hi, uint2& lo) {
    __nv_bfloat16 hx = __float2bfloat16(v.x), hy = __float2bfloat16(v.y);
    __nv_bfloat16 hz = __float2bfloat16(v.z), hw = __float2bfloat16(v.w);
    __nv_bfloat16 lx = __float2bfloat16(v.x - __bfloat162float(hx));
    __nv_bfloat16 ly = __float2bfloat16(v.y - __bfloat162float(hy));
    __nv_bfloat16 lz = __float2bfloat16(v.z - __bfloat162float(hz));
    __nv_bfloat16 lw = __float2bfloat16(v.w - __bfloat162float(hw));
    __nv_bfloat162 h0 = __halves2bfloat162(hx, hy), h1 = __halves2bfloat162(hz, hw);
    __nv_bfloat162 l0 = __halves2bfloat162(lx, ly), l1 = __halves2bfloat162(lz, lw);
    hi.x = *(uint32_t*)&h0; hi.y = *(uint32_t*)&h1;
    lo.x = *(uint32_t*)&l0; lo.y = *(uint32_t*)&l1;
}

// ---------------- bf16 hi/lo NT GEMM on mma.sync, register-pipelined -------
// C[m][n] = sum_k A[m][k]*B[n][k] (both K-contiguous), + bias, + leaky.
// Block 128 x BN, BK=32. 8 warps: 2(m) x 4(n); warp tile 64 x (BN/4).
// hi*hi + hi*lo + lo*hi accumulation in fp32. Next chunk's global loads are
// issued BEFORE the MMA loop of the current chunk (register double buffer).
template <int BN, bool HAS_BIAS, bool LEAKY>
__global__ __launch_bounds__(256) void mgemm(
    const float* __restrict__ A, int lda, long aZ,
    const float* __restrict__ Bm, int ldb, long bZ,
    const float* __restrict__ bias, int biasZ,
    float* __restrict__ C, int ldc, long cZ,
    int K)
{
    constexpr int P  = 40;              // smem pitch in bf16 (32 + 8 pad)
    constexpr int NF = BN / 32;         // n8-frags per warp (warp n-tile = BN/4)
    constexpr int NB = BN / 32;         // B staging float4s per thread

    __shared__ __align__(16) uint16_t sAhi[128 * P];
    __shared__ __align__(16) uint16_t sAlo[128 * P];
    __shared__ __align__(16) uint16_t sBhi[BN * P];
    __shared__ __align__(16) uint16_t sBlo[BN * P];

    const int tid  = threadIdx.x;
    const int wid  = tid >> 5;
    const int lane = tid & 31;
    const int g    = lane >> 2;         // 0..7
    const int tig  = lane & 3;          // 0..3
    const int wm   = wid & 1;           // m-warp (0..1)
    const int wn   = wid >> 1;          // n-warp (0..3)

    const int z = blockIdx.z;
    A  += (long)z * aZ;
    Bm += (long)z * bZ;
    C  += (long)z * cZ;
    const float* bp = HAS_BIAS ? (bias + (long)z * biasZ) : nullptr;
    const int m0 = blockIdx.y * 128;
    const int n0 = blockIdx.x * BN;

    // staging thread mapping (row = idx>>3, col4 = (idx&7)*4)
    const int srow = tid >> 3;
    const int sc4  = (tid & 7) << 2;

    float4 aR[4], bR[NB];
    auto ldg = [&](int c) {
        const int k0 = c << 5;
#pragma unroll
        for (int i = 0; i < 4; i++)
            aR[i] = *(const float4*)(A + (long)(m0 + srow + 32 * i) * lda + k0 + sc4);
#pragma unroll
        for (int i = 0; i < NB; i++)
            bR[i] = *(const float4*)(Bm + (long)(n0 + srow + 32 * i) * ldb + k0 + sc4);
    };
    auto sts = [&]() {
#pragma unroll
        for (int i = 0; i < 4; i++) {
            uint2 hi, lo;
            cvt_split(aR[i], hi, lo);
            *(uint2*)(sAhi + (srow + 32 * i) * P + sc4) = hi;
            *(uint2*)(sAlo + (srow + 32 * i) * P + sc4) = lo;
        }
#pragma unroll
        for (int i = 0; i < NB; i++) {
            uint2 hi, lo;
            cvt_split(bR[i], hi, lo);
            *(uint2*)(sBhi + (srow + 32 * i) * P + sc4) = hi;
            *(uint2*)(sBlo + (srow + 32 * i) * P + sc4) = lo;
        }
    };

    float acc[4][NF][4];
#pragma unroll
    for (int mf = 0; mf < 4; mf++)
#pragma unroll
        for (int nf = 0; nf < NF; nf++)
#pragma unroll
            for (int j = 0; j < 4; j++) acc[mf][nf][j] = 0.0f;

    const int nchunk = K >> 5;          // BK = 32
    ldg(0);
    sts();
    __syncthreads();

    for (int c = 0; c < nchunk; c++) {
        const bool more = (c + 1 < nchunk);
        if (more) ldg(c + 1);           // in flight during MMA loop

        // ---- compute: two k16 steps from current smem
#pragma unroll
        for (int kk = 0; kk < 32; kk += 16) {
            const int co = kk + 2 * tig;
            uint32_t ah[4][4], al[4][4];
#pragma unroll
            for (int mf = 0; mf < 4; mf++) {
                const int r = wm * 64 + mf * 16 + g;
                ah[mf][0] = *(const uint32_t*)(sAhi + r * P + co);
                ah[mf][1] = *(const uint32_t*)(sAhi + (r + 8) * P + co);
                ah[mf][2] = *(const uint32_t*)(sAhi + r * P + co + 8);
                ah[mf][3] = *(const uint32_t*)(sAhi + (r + 8) * P + co + 8);
                al[mf][0] = *(const uint32_t*)(sAlo + r * P + co);
                al[mf][1] = *(const uint32_t*)(sAlo + (r + 8) * P + co);
                al[mf][2] = *(const uint32_t*)(sAlo + r * P + co + 8);
                al[mf][3] = *(const uint32_t*)(sAlo + (r + 8) * P + co + 8);
            }
            uint32_t bh[NF][2], bl[NF][2];
#pragma unroll
            for (int nf = 0; nf < NF; nf++) {
                const int n = wn * (BN / 4) + nf * 8 + g;
                bh[nf][0] = *(const uint32_t*)(sBhi + n * P + co);
                bh[nf][1] = *(const uint32_t*)(sBhi + n * P + co + 8);
                bl[nf][0] = *(const uint32_t*)(sBlo + n * P + co);
                bl[nf][1] = *(const uint32_t*)(sBlo + n * P + co + 8);
            }
#pragma unroll
            for (int mf = 0; mf < 4; mf++)
#pragma unroll
                for (int nf = 0; nf < NF; nf++) {
                    mma16816(acc[mf][nf], ah[mf], bh[nf]);
                    mma16816(acc[mf][nf], ah[mf], bl[nf]);
                    mma16816(acc[mf][nf], al[mf], bh[nf]);
                }
        }

        if (more) {
            __syncthreads();            // everyone done reading smem
            sts();                      // overwrite with next chunk
            __syncthreads();            // staging visible
        }
    }

    // ---- epilogue
#pragma unroll
    for (int mf = 0; mf < 4; mf++) {
        const int row = m0 + wm * 64 + mf * 16 + g;
#pragma unroll
        for (int nf = 0; nf < NF; nf++) {
            const int col = n0 + wn * (BN / 4) + nf * 8 + 2 * tig;
            float b0 = 0.0f, b1 = 0.0f;
            if (HAS_BIAS) { b0 = bp[col]; b1 = bp[col + 1]; }
            float x0 = acc[mf][nf][0] + b0, x1 = acc[mf][nf][1] + b1;
            float x2 = acc[mf][nf][2] + b0, x3 = acc[mf][nf][3] + b1;
            if (LEAKY) {
                x0 = x0 > 0.0f ? x0 : 0.01f * x0;
                x1 = x1 > 0.0f ? x1 : 0.01f * x1;
                x2 = x2 > 0.0f ? x2 : 0.01f * x2;
                x3 = x3 > 0.0f ? x3 : 0.01f * x3;
            }
            float2 v0; v0.x = x0; v0.y = x1;
            float2 v1; v1.x = x2; v1.y = x3;
            *(float2*)(C + (long)row * ldc + col)       = v0;
            *(float2*)(C + (long)(row + 8) * ldc + col) = v1;
        }
    }
}

// ---------------- Wc split-K reduction -------------------------------------
__global__ void wc_reduce(const float4* __restrict__ p, float4* __restrict__ o)
{
    const int i = blockIdx.x * 256 + threadIdx.x;      // 0..32767
    float4 a = p[i], b = p[i + 32768], c = p[i + 65536], d = p[i + 98304];
    float4 r;
    r.x = a.x + b.x + c.x + d.x;
    r.y = a.y + b.y + c.y + d.y;
    r.z = a.z + b.z + c.z + d.z;
    r.w = a.w + b.w + c.w + d.w;
    o[i] = r;
}

// ---------------- 512x512 transpose ----------------------------------------
__global__ void transp512(const float* __restrict__ in, float* __restrict__ out)
{
    __shared__ float t[32][33];
    const int x = blockIdx.x * 32 + threadIdx.x;
    const int y0 = blockIdx.y * 32;
#pragma unroll
    for (int r = threadIdx.y; r < 32; r += 8)
        t[r][threadIdx.x] = in[(y0 + r) * 512 + x];
    __syncthreads();
    const int xo = blockIdx.y * 32 + threadIdx.x;
#pragma unroll
    for (int r = threadIdx.y; r < 32; r += 8)
        out[(blockIdx.x * 32 + r) * 512 + xo] = t[threadIdx.x][r];
}

// ---------------- fused per-node attention: scores -> softmax -> kbar ------
__global__ __launch_bounds__(256) void attn2(
    const float* __restrict__ keys,   // [S,B,D]
    const float* __restrict__ qt,     // [B,H,D]
    float* __restrict__ kbar)         // [B,H,D]
{
    __shared__ __align__(16) float sk[Sc][Dc];     // 40 KB
    __shared__ __align__(16) float attnT[Sc][Hc];  // transposed weights

    const int b   = blockIdx.x;
    const int tid = threadIdx.x;

#pragma unroll
    for (int i = 0; i < 10; i++) {
        const int idx = tid + 256 * i;
        const int s = idx >> 7;
        const int v = idx & 127;
        ((float4*)sk)[idx] = ((const float4*)(keys + ((size_t)s * Bc + b) * Dc))[v];
    }
    __syncthreads();

    const int w = tid >> 5;
    const int l = tid & 31;

    const float* qrow = qt + (size_t)b * (Hc * Dc) + w * Dc;
    float4 qf[4];
#pragma unroll
    for (int j = 0; j < 4; j++)
        qf[j] = *(const float4*)(qrow + 128 * j + 4 * l);

    float sc[Sc];
    float mx = -1e30f;
#pragma unroll
    for (int s = 0; s < Sc; s++) {
        const float4* kr = (const float4*)&sk[s][0];
        float p = 0.0f;
#pragma unroll
        for (int j = 0; j < 4; j++) {
            float4 kv = kr[32 * j + l];
            p = fmaf(qf[j].x, kv.x, p);
            p = fmaf(qf[j].y, kv.y, p);
            p = fmaf(qf[j].z, kv.z, p);
            p = fmaf(qf[j].w, kv.w, p);
        }
#pragma unroll
        for (int o = 16; o > 0; o >>= 1) p += __shfl_xor_sync(0xffffffffu, p, o);
        sc[s] = p * 0.125f;
        mx = fmaxf(mx, sc[s]);
    }

    float sum = 0.0f;
#pragma unroll
    for (int s = 0; s < Sc; s++) { sc[s] = expf(sc[s] - mx); sum += sc[s]; }
    const float inv = 1.0f / sum;
    if (l == 0) {
#pragma unroll
        for (int s = 0; s < Sc; s++) attnT[s][w] = sc[s] * inv;
    }
    __syncthreads();

    float2 acc[Hc];
#pragma unroll
    for (int h = 0; h < Hc; h++) { acc[h].x = 0.0f; acc[h].y = 0.0f; }

    const float2* sk2 = (const float2*)sk;
#pragma unroll
    for (int s = 0; s < Sc; s++) {
        const float2 kv = sk2[s * (Dc / 2) + tid];
        const float4 a0 = *(const float4*)&attnT[s][0];
        const float4 a1 = *(const float4*)&attnT[s][4];
        acc[0].x = fmaf(a0.x, kv.x, acc[0].x); acc[0].y = fmaf(a0.x, kv.y, acc[0].y);
        acc[1].x = fmaf(a0.y, kv.x, acc[1].x); acc[1].y = fmaf(a0.y, kv.y, acc[1].y);
        acc[2].x = fmaf(a0.z, kv.x, acc[2].x); acc[2].y = fmaf(a0.z, kv.y, acc[2].y);
        acc[3].x = fmaf(a0.w, kv.x, acc[3].x); acc[3].y = fmaf(a0.w, kv.y, acc[3].y);
        acc[4].x = fmaf(a1.x, kv.x, acc[4].x); acc[4].y = fmaf(a1.x, kv.y, acc[4].y);
        acc[5].x = fmaf(a1.y, kv.x, acc[5].x); acc[5].y = fmaf(a1.y, kv.y, acc[5].y);
        acc[6].x = fmaf(a1.z, kv.x, acc[6].x); acc[6].y = fmaf(a1.z, kv.y, acc[6].y);
        acc[7].x = fmaf(a1.w, kv.x, acc[7].x); acc[7].y = fmaf(a1.w, kv.y, acc[7].y);
    }

    float* kb = kbar + (size_t)b * (Hc * Dc);
#pragma unroll
    for (int h = 0; h < Hc; h++)
        *(float2*)(kb + h * Dc + 2 * tid) = acc[h];
}

// ---------------- fused bias: bc = lin_w @ b_o + lin_b ---------------------
__global__ void bc_kernel(const float* __restrict__ lin_w,
                          const float* __restrict__ opb,
                          const float* __restrict__ lin_b,
                          float* __restrict__ bc)
{
    const int e = threadIdx.x;
    if (e < Ec) {
        float a = lin_b[e];
        const float4* row = (const float4*)(lin_w + (size_t)e * Dc);
        const float4* ob  = (const float4*)opb;
        for (int d = 0; d < Dc / 4; d++) {
            float4 r = row[d], v = ob[d];
            a = fmaf(r.x, v.x, a); a = fmaf(r.y, v.y, a);
            a = fmaf(r.z, v.z, a); a = fmaf(r.w, v.w, a);
        }
        bc[e] = a;
    }
}

// ---------------- launch ---------------------------------------------------
extern "C" void kernel_launch(void* const* d_in, const int* in_sizes, int n_in,
                              void* d_out, int out_size)
{
    const float* query = (const float*)d_in[0];   // [1,B,D]
    const float* keys  = (const float*)d_in[1];   // [S,B,D]
    const float* ipw   = (const float*)d_in[2];   // [3D,D]
    const float* ipb   = (const float*)d_in[3];   // [3D]
    const float* opw   = (const float*)d_in[4];   // [D,D]
    const float* opb   = (const float*)d_in[5];   // [D]
    const float* lw    = (const float*)d_in[6];   // [E,D]
    const float* lb    = (const float*)d_in[7];   // [E]
    float* out = (float*)d_out;                   // [B,E]

    float *qh, *qt, *kbar, *ctx, *Wc, *Wcp, *bc, *WkT, *opwT;
    cudaGetSymbolAddress((void**)&qh,   g_qh);
    cudaGetSymbolAddress((void**)&qt,   g_qt);
    cudaGetSymbolAddress((void**)&kbar, g_kbar);
    cudaGetSymbolAddress((void**)&ctx,  g_ctx);
    cudaGetSymbolAddress((void**)&Wc,   g_Wc);
    cudaGetSymbolAddress((void**)&Wcp,  g_Wcp);
    cudaGetSymbolAddress((void**)&bc,   g_bc);
    cudaGetSymbolAddress((void**)&WkT,  g_WkT);
    cudaGetSymbolAddress((void**)&opwT, g_opwT);

    dim3 t(256);

    // T: transposes (WkT = Wk^T, opwT = out_proj_w^T) + fused bias
    transp512<<<dim3(16, 16), dim3(32, 8)>>>(ipw + (size_t)Dc * Dc, WkT);
    transp512<<<dim3(16, 16), dim3(32, 8)>>>(opw, opwT);
    bc_kernel<<<1, 256>>>(lw, opb, lb, bc);

    // K0: Wc = lin_w @ opwT^T, split-K z=4  (NT, M=256, N=512, K=128/part)
    mgemm<128, false, false><<<dim3(4, 2, 4), t>>>(
        lw, Dc, 128,
        opwT, Dc, 128,
        nullptr, 0,
        Wcp, Dc, (long)Ec * Dc,
        128);
    wc_reduce<<<128, 256>>>((const float4*)Wcp, (float4*)Wc);

    // K1: qh = query @ Wq^T + bq   (NT, M=8192, N=512, K=512)
    mgemm<128, true, false><<<dim3(4, Bc / 128, 1), t>>>(
        query, Dc, 0,  ipw, Dc, 0,  ipb, 0,  qh, Dc, 0,  Dc);

    // K2: qt[b,h,:] = Wk_h^T qh_h  (NT per head, M=8192, N=512, K=64)
    mgemm<128, false, false><<<dim3(4, Bc / 128, Hc), t>>>(
        qh, Dc, HDc,
        WkT, Dc, HDc,
        nullptr, 0,
        qt, Hc * Dc, Dc,
        HDc);

    // K3: fused scores/softmax/kbar
    attn2<<<Bc, 256>>>(keys, qt, kbar);

    // K4: ctx[b,h-slice] = Wv_h kbar_h + bv (NT per head, M=8192, N=64, K=512)
    mgemm<64, true, false><<<dim3(1, Bc / 128, Hc), t>>>(
        kbar, Hc * Dc, Dc,
        ipw + (size_t)2 * Dc * Dc, Dc, (long)HDc * Dc,
        ipb + 2 * Dc, HDc,
        ctx, Dc, HDc,
        Dc);

    // K5: y = LeakyReLU(ctx @ Wc^T + bc)  (NT, M=8192, N=256, K=512)
    mgemm<128, true, true><<<dim3(2, Bc / 128, 1), t>>>(
        ctx, Dc, 0,  Wc, Dc, 0,  bc, 0,  out, Ec, 0,  Dc);
}